// round 12
// baseline (speedup 1.0000x reference)
#include <cuda_runtime.h>
#include <cstdint>
#include <cstddef>

// CRF forward log-partition. B=512, T=1024, L=64.
// Fwd/bwd split halves the serial chain; TWO batches per 128-thread CTA so
// all 4 SMSPs get warps (64-thread CTAs left SMSP 2,3 idle -> issue-bound):
//   warp 0: fwd b0   warp 1: bwd b0   warp 2: fwd b1   warp 3: bwd b1
// Z = e63^T M_{len-1}..M_0 delta,  M_t = diag(el_t) E.
//   fwd: p = M_{m-1}..M_0 delta_start      (m = len/2 steps)
//   bwd: v = M_m^T..M_{len-1}^T e63        (len-m steps, E^T in registers)
// logZ = (ktF+ktB)*ln2 + log( sum_j p[j] * v[j] )
//
// Step core source-forced (volatile asm): 16x ld.shared.v2.b64 front-batch,
// 8 named f32x2 accumulators, st.shared.b64. Rescale every 4 steps, fully
// deferred (RECORD: REDUX -> mu with no consumer; FOLD next group: exact
// 2^-k folded into exp(logit) computed at step top from prefetched logit).

#define CRF_B 512
#define CRF_T 1024
#define CRF_L 64
#define C_LOG2E 1.4426950408889634f
#define C_LN2   0.6931471805599453f
#define FULLM  0xffffffffu

using u64 = unsigned long long;

__device__ __forceinline__ float ex2f(float x) {
    float r; asm("ex2.approx.f32 %0, %1;" : "=f"(r) : "f"(x)); return r;
}
__device__ __forceinline__ u64 packf2(float lo, float hi) {
    u64 r; asm("mov.b64 %0, {%1, %2};" : "=l"(r) : "f"(lo), "f"(hi)); return r;
}
__device__ __forceinline__ void unpackf2(u64 v, float& lo, float& hi) {
    asm("mov.b64 {%0, %1}, %2;" : "=f"(lo), "=f"(hi) : "l"(v));
}
__device__ __forceinline__ uint32_t smem_u32(const void* p) {
    uint32_t a;
    asm("{ .reg .u64 t; cvta.to.shared.u64 t, %1; cvt.u32.u64 %0, t; }"
        : "=r"(a) : "l"(p));
    return a;
}
#define FMA2(acc, a, b) \
    asm("fma.rn.f32x2 %0, %1, %2, %0;" : "+l"(acc) : "l"(a), "l"(b))
#define ADD2(acc, a) \
    asm("add.rn.f32x2 %0, %0, %1;" : "+l"(acc) : "l"(a))
#define LDSV2(lo, hi, addr) \
    asm volatile("ld.shared.v2.b64 {%0, %1}, [%2];" \
                 : "=l"(lo), "=l"(hi) : "r"(addr))

// One CRF step (R11 verbatim). FOLD: consume mu (recorded 3+ steps ago),
// fold exact 2^-k into el. REC: REDUX.MAX of new p into mu (no consumer).
template <bool FOLD, bool REC>
__device__ __forceinline__ void crf_step(
    float2 lg,
    const u64 (&Ea)[32], const u64 (&Eb)[32],
    uint32_t rda, uint32_t wra,
    int lane, int& ktot, unsigned& mu)
{
    float elA = ex2f(lg.x * C_LOG2E);
    float elB = ex2f(lg.y * C_LOG2E);
    if (FOLD) {
        int k = (int)(mu >> 23) - 127;
        ktot += k;
        float s = __int_as_float((127 - k) << 23);   // exact 2^-k
        elA *= s;
        elB *= s;
    }

    u64 p[32];
#pragma unroll
    for (int i = 0; i < 16; i++)
        LDSV2(p[2 * i], p[2 * i + 1], rda + 16u * i);

    u64 a0 = 0ull, a1 = 0ull, a2 = 0ull, a3 = 0ull;
    u64 b0 = 0ull, b1 = 0ull, b2 = 0ull, b3 = 0ull;
#pragma unroll
    for (int jj = 0; jj < 32; jj += 4) {
        FMA2(a0, Ea[jj],     p[jj]);
        FMA2(b0, Eb[jj],     p[jj]);
        FMA2(a1, Ea[jj + 1], p[jj + 1]);
        FMA2(b1, Eb[jj + 1], p[jj + 1]);
        FMA2(a2, Ea[jj + 2], p[jj + 2]);
        FMA2(b2, Eb[jj + 2], p[jj + 2]);
        FMA2(a3, Ea[jj + 3], p[jj + 3]);
        FMA2(b3, Eb[jj + 3], p[jj + 3]);
    }
    ADD2(a0, a1); ADD2(a2, a3); ADD2(a0, a2);
    ADD2(b0, b1); ADD2(b2, b3); ADD2(b0, b2);
    float ax, ay, bx, by;
    unpackf2(a0, ax, ay);
    unpackf2(b0, bx, by);
    float pA = (ax + ay) * elA;
    float pB = (bx + by) * elB;

    asm volatile("st.shared.b64 [%0], %1;"
                 :: "r"(wra + 8u * (uint32_t)lane), "l"(packf2(pA, pB)));

    if (REC) {
        mu = __reduce_max_sync(FULLM, __float_as_uint(fmaxf(pA, pB)));
    }
    __syncwarp();
}

template <int SGN>
__device__ __forceinline__ int run_chain(
    const float2* __restrict__ lgp, int nlog, bool bare,
    const u64 (&Ea)[32], const u64 (&Eb)[32],
    uint32_t b0a, uint32_t b1a, int lane)
{
    int      ktot = 0;
    unsigned mu   = 0x3f800000u;           // 1.0f bits -> first fold k=0

    float2 q0, q1, q2, q3;
    if (nlog > 0) q0 = __ldg(lgp);
    if (nlog > 1) q1 = __ldg(lgp + SGN * 32);
    if (nlog > 2) q2 = __ldg(lgp + SGN * 64);
    if (nlog > 3) q3 = __ldg(lgp + SGN * 96);

    int t = 0;
    for (; t + 4 <= nlog; t += 4) {
        float2 g;
        g = q0; if (t + 4 < nlog) q0 = __ldg(lgp + (ptrdiff_t)SGN * (t + 4) * 32);
        crf_step<true,  false>(g, Ea, Eb, b0a, b1a, lane, ktot, mu);
        g = q1; if (t + 5 < nlog) q1 = __ldg(lgp + (ptrdiff_t)SGN * (t + 5) * 32);
        crf_step<false, false>(g, Ea, Eb, b1a, b0a, lane, ktot, mu);
        g = q2; if (t + 6 < nlog) q2 = __ldg(lgp + (ptrdiff_t)SGN * (t + 6) * 32);
        crf_step<false, false>(g, Ea, Eb, b0a, b1a, lane, ktot, mu);
        g = q3; if (t + 7 < nlog) q3 = __ldg(lgp + (ptrdiff_t)SGN * (t + 7) * 32);
        crf_step<false, true >(g, Ea, Eb, b1a, b0a, lane, ktot, mu);
    }

    bool pend = (t > 0);
    if (t < nlog) {
        if (pend) crf_step<true,  false>(q0, Ea, Eb, b0a, b1a, lane, ktot, mu);
        else      crf_step<false, false>(q0, Ea, Eb, b0a, b1a, lane, ktot, mu);
        pend = false; t++;
    }
    if (t < nlog) { crf_step<false, false>(q1, Ea, Eb, b1a, b0a, lane, ktot, mu); t++; }
    if (t < nlog) { crf_step<false, false>(q2, Ea, Eb, b0a, b1a, lane, ktot, mu); t++; }

    if (bare) {
        float2 g = make_float2(0.0f, 0.0f);
        bool odd = (t & 1);
        if (pend) {
            if (odd) crf_step<true, false>(g, Ea, Eb, b1a, b0a, lane, ktot, mu);
            else     crf_step<true, false>(g, Ea, Eb, b0a, b1a, lane, ktot, mu);
        } else {
            if (odd) crf_step<false, false>(g, Ea, Eb, b1a, b0a, lane, ktot, mu);
            else     crf_step<false, false>(g, Ea, Eb, b0a, b1a, lane, ktot, mu);
        }
    }
    return ktot;
}

__global__ void __launch_bounds__(128)
crf_fwd_kernel(const float* __restrict__ logits,
               const int*   __restrict__ lens,
               const float* __restrict__ trans,
               float*       __restrict__ out)
{
    __shared__ __align__(16) float2 sp[4][2][32];   // [warp][buffer][pair]
    __shared__ float2 fin[4][32];
    __shared__ int    ktW[4];

    const int w    = threadIdx.x >> 5;              // 0..3
    const int lane = threadIdx.x & 31;
    const int b    = blockIdx.x * 2 + (w >> 1);     // grid=256 -> b < 512
    const int dir  = w & 1;                         // 0 = fwd, 1 = bwd

    const uint32_t b0a = smem_u32(sp[w][0]);
    const uint32_t b1a = smem_u32(sp[w][1]);
    u64* wr0 = reinterpret_cast<u64*>(sp[w][0]);
    u64* wr1 = reinterpret_cast<u64*>(sp[w][1]);

    const int len = lens[b];
    const int m   = len >> 1;                       // fwd steps; bwd = len-m

    // ---- E in registers: fwd = rows of exp(trans); bwd = columns ----
    u64 Ea[32], Eb[32];
    if (dir == 0) {
        const float* ra = trans + (2 * lane)     * CRF_L;
        const float* rb = trans + (2 * lane + 1) * CRF_L;
#pragma unroll
        for (int jj = 0; jj < 32; jj++) {
            Ea[jj] = packf2(expf(ra[2 * jj]), expf(ra[2 * jj + 1]));
            Eb[jj] = packf2(expf(rb[2 * jj]), expf(rb[2 * jj + 1]));
        }
    } else {
        const float* ca = trans + (2 * lane);       // column 2*lane
        const float* cb = trans + (2 * lane + 1);   // column 2*lane+1
#pragma unroll
        for (int jj = 0; jj < 32; jj++) {
            Ea[jj] = packf2(expf(ca[(2 * jj) * CRF_L]), expf(ca[(2 * jj + 1) * CRF_L]));
            Eb[jj] = packf2(expf(cb[(2 * jj) * CRF_L]), expf(cb[(2 * jj + 1) * CRF_L]));
        }
    }

    const float2* base =
        reinterpret_cast<const float2*>(logits + (size_t)b * CRF_T * CRF_L) + lane;

    int kt;
    int nsteps;

    if (dir == 0) {
        // ---- forward: init = delta at start label 62, m logit steps ----
        wr0[lane] = packf2((2 * lane == 62) ? 1.0f : 0.0f,
                           (2 * lane + 1 == 62) ? 1.0f : 0.0f);
        __syncwarp();
        kt = run_chain<+1>(base, m, false, Ea, Eb, b0a, b1a, lane);
        nsteps = m;
    } else {
        // ---- backward: init v = el_{len-1} .* e63 (or e63 if len==0) ----
        float e63x = expf(trans[63 * CRF_L + 2 * lane]);
        float e63y = expf(trans[63 * CRF_L + 2 * lane + 1]);
        if (len >= 1) {
            float2 lgl = __ldg(base + (ptrdiff_t)(len - 1) * 32);
            e63x *= expf(lgl.x);
            e63y *= expf(lgl.y);
        }
        wr0[lane] = packf2(e63x, e63y);
        __syncwarp();
        const int nlog = (len >= 1) ? (len - m - 1) : 0;
        const float2* lgb = base + (ptrdiff_t)(len - 2) * 32;
        kt = run_chain<-1>(lgb, nlog, len >= 1, Ea, Eb, b0a, b1a, lane);
        nsteps = (len >= 1) ? (nlog + 1) : 0;
    }

    // ---- combine per batch: logZ = (ktF+ktB)*ln2 + log(sum pF[j]*pB[j]) ----
    float px, py;
    unpackf2((nsteps & 1) ? wr1[lane] : wr0[lane], px, py);
    fin[w][lane] = make_float2(px, py);
    if (lane == 0) ktW[w] = kt;
    __syncthreads();

    if (dir == 0) {
        float2 f = fin[w][lane];
        float2 g = fin[w + 1][lane];
        float dot = f.x * g.x + f.y * g.y;
#pragma unroll
        for (int o = 16; o > 0; o >>= 1)
            dot += __shfl_xor_sync(FULLM, dot, o);
        if (lane == 0)
            out[b] = (float)(ktW[w] + ktW[w + 1]) * C_LN2 + __logf(dot);
    }
}

extern "C" void kernel_launch(void* const* d_in, const int* in_sizes, int n_in,
                              void* d_out, int out_size)
{
    const float* logits = (const float*)d_in[0];   // [512,1024,64] f32
    const int*   lens   = (const int*)  d_in[1];   // [512] i32
    const float* trans  = (const float*)d_in[2];   // [64,64] f32
    float* out = (float*)d_out;                    // [512] f32

    crf_fwd_kernel<<<CRF_B / 2, 128>>>(logits, lens, trans, out);
}

// round 13
// speedup vs baseline: 1.1276x; 1.1276x over previous
#include <cuda_runtime.h>
#include <cstdint>
#include <cstddef>

// CRF forward log-partition. B=512, T=1024, L=64.
// Fwd/bwd split (halves the serial chain) + LENGTH-AWARE PLACEMENT:
// a pre-kernel ranks batches by len (descending); the main kernel maps
// rank -> blockIdx in a snake over the 148 bid%148 residue classes (the
// classic scheduler's SM mapping), so each SM hosts one long chain plus
// mid/short companions. The critical chain runs most of its steps with the
// SM to itself; per-SM total work is balanced.
//
// Main kernel core = Round-11 verbatim (source-forced front-batching:
// 16x ld.shared.v2.b64, 8 named f32x2 accumulators, deferred 4-step exact
// power-of-2 rescale).  logZ = (ktF+ktB)*ln2 + log(sum_j pF[j]*pB[j]).

#define CRF_B 512
#define CRF_T 1024
#define CRF_L 64
#define C_LOG2E 1.4426950408889634f
#define C_LN2   0.6931471805599453f
#define FULLM  0xffffffffu

using u64 = unsigned long long;

__device__ int d_perm[CRF_B];            // rank -> batch index

__device__ __forceinline__ float ex2f(float x) {
    float r; asm("ex2.approx.f32 %0, %1;" : "=f"(r) : "f"(x)); return r;
}
__device__ __forceinline__ u64 packf2(float lo, float hi) {
    u64 r; asm("mov.b64 %0, {%1, %2};" : "=l"(r) : "f"(lo), "f"(hi)); return r;
}
__device__ __forceinline__ void unpackf2(u64 v, float& lo, float& hi) {
    asm("mov.b64 {%0, %1}, %2;" : "=f"(lo), "=f"(hi) : "l"(v));
}
__device__ __forceinline__ uint32_t smem_u32(const void* p) {
    uint32_t a;
    asm("{ .reg .u64 t; cvta.to.shared.u64 t, %1; cvt.u32.u64 %0, t; }"
        : "=r"(a) : "l"(p));
    return a;
}
#define FMA2(acc, a, b) \
    asm("fma.rn.f32x2 %0, %1, %2, %0;" : "+l"(acc) : "l"(a), "l"(b))
#define ADD2(acc, a) \
    asm("add.rn.f32x2 %0, %0, %1;" : "+l"(acc) : "l"(a))
#define LDSV2(lo, hi, addr) \
    asm volatile("ld.shared.v2.b64 {%0, %1}, [%2];" \
                 : "=l"(lo), "=l"(hi) : "r"(addr))

// ---- pre-kernel: exact descending-length ranking (O(n^2) count) ----
__global__ void __launch_bounds__(CRF_B)
rank_kernel(const int* __restrict__ lens)
{
    __shared__ int sl[CRF_B];
    const int i = threadIdx.x;
    sl[i] = lens[i];
    __syncthreads();
    const int li = sl[i];
    int cnt = 0;
#pragma unroll 8
    for (int j = 0; j < CRF_B; j++) {
        int lj = sl[j];
        cnt += (lj > li) || (lj == li && j < i);
    }
    d_perm[cnt] = i;                      // bijection: rank -> batch
}

// ---- R11 step, verbatim ----
template <bool FOLD, bool REC>
__device__ __forceinline__ void crf_step(
    float2 lg,
    const u64 (&Ea)[32], const u64 (&Eb)[32],
    uint32_t rda, uint32_t wra,
    int lane, int& ktot, unsigned& mu)
{
    float elA = ex2f(lg.x * C_LOG2E);
    float elB = ex2f(lg.y * C_LOG2E);
    if (FOLD) {
        int k = (int)(mu >> 23) - 127;
        ktot += k;
        float s = __int_as_float((127 - k) << 23);   // exact 2^-k
        elA *= s;
        elB *= s;
    }

    u64 p[32];
#pragma unroll
    for (int i = 0; i < 16; i++)
        LDSV2(p[2 * i], p[2 * i + 1], rda + 16u * i);

    u64 a0 = 0ull, a1 = 0ull, a2 = 0ull, a3 = 0ull;
    u64 b0 = 0ull, b1 = 0ull, b2 = 0ull, b3 = 0ull;
#pragma unroll
    for (int jj = 0; jj < 32; jj += 4) {
        FMA2(a0, Ea[jj],     p[jj]);
        FMA2(b0, Eb[jj],     p[jj]);
        FMA2(a1, Ea[jj + 1], p[jj + 1]);
        FMA2(b1, Eb[jj + 1], p[jj + 1]);
        FMA2(a2, Ea[jj + 2], p[jj + 2]);
        FMA2(b2, Eb[jj + 2], p[jj + 2]);
        FMA2(a3, Ea[jj + 3], p[jj + 3]);
        FMA2(b3, Eb[jj + 3], p[jj + 3]);
    }
    ADD2(a0, a1); ADD2(a2, a3); ADD2(a0, a2);
    ADD2(b0, b1); ADD2(b2, b3); ADD2(b0, b2);
    float ax, ay, bx, by;
    unpackf2(a0, ax, ay);
    unpackf2(b0, bx, by);
    float pA = (ax + ay) * elA;
    float pB = (bx + by) * elB;

    asm volatile("st.shared.b64 [%0], %1;"
                 :: "r"(wra + 8u * (uint32_t)lane), "l"(packf2(pA, pB)));

    if (REC) {
        mu = __reduce_max_sync(FULLM, __float_as_uint(fmaxf(pA, pB)));
    }
    __syncwarp();
}

template <int SGN>
__device__ __forceinline__ int run_chain(
    const float2* __restrict__ lgp, int nlog, bool bare,
    const u64 (&Ea)[32], const u64 (&Eb)[32],
    uint32_t b0a, uint32_t b1a, int lane)
{
    int      ktot = 0;
    unsigned mu   = 0x3f800000u;           // 1.0f bits -> first fold k=0

    float2 q0, q1, q2, q3;
    if (nlog > 0) q0 = __ldg(lgp);
    if (nlog > 1) q1 = __ldg(lgp + SGN * 32);
    if (nlog > 2) q2 = __ldg(lgp + SGN * 64);
    if (nlog > 3) q3 = __ldg(lgp + SGN * 96);

    int t = 0;
    for (; t + 4 <= nlog; t += 4) {
        float2 g;
        g = q0; if (t + 4 < nlog) q0 = __ldg(lgp + (ptrdiff_t)SGN * (t + 4) * 32);
        crf_step<true,  false>(g, Ea, Eb, b0a, b1a, lane, ktot, mu);
        g = q1; if (t + 5 < nlog) q1 = __ldg(lgp + (ptrdiff_t)SGN * (t + 5) * 32);
        crf_step<false, false>(g, Ea, Eb, b1a, b0a, lane, ktot, mu);
        g = q2; if (t + 6 < nlog) q2 = __ldg(lgp + (ptrdiff_t)SGN * (t + 6) * 32);
        crf_step<false, false>(g, Ea, Eb, b0a, b1a, lane, ktot, mu);
        g = q3; if (t + 7 < nlog) q3 = __ldg(lgp + (ptrdiff_t)SGN * (t + 7) * 32);
        crf_step<false, true >(g, Ea, Eb, b1a, b0a, lane, ktot, mu);
    }

    bool pend = (t > 0);
    if (t < nlog) {
        if (pend) crf_step<true,  false>(q0, Ea, Eb, b0a, b1a, lane, ktot, mu);
        else      crf_step<false, false>(q0, Ea, Eb, b0a, b1a, lane, ktot, mu);
        pend = false; t++;
    }
    if (t < nlog) { crf_step<false, false>(q1, Ea, Eb, b1a, b0a, lane, ktot, mu); t++; }
    if (t < nlog) { crf_step<false, false>(q2, Ea, Eb, b0a, b1a, lane, ktot, mu); t++; }

    if (bare) {
        float2 g = make_float2(0.0f, 0.0f);
        bool odd = (t & 1);
        if (pend) {
            if (odd) crf_step<true, false>(g, Ea, Eb, b1a, b0a, lane, ktot, mu);
            else     crf_step<true, false>(g, Ea, Eb, b0a, b1a, lane, ktot, mu);
        } else {
            if (odd) crf_step<false, false>(g, Ea, Eb, b1a, b0a, lane, ktot, mu);
            else     crf_step<false, false>(g, Ea, Eb, b0a, b1a, lane, ktot, mu);
        }
    }
    return ktot;
}

__global__ void __launch_bounds__(64)
crf_fwd_kernel(const float* __restrict__ logits,
               const int*   __restrict__ lens,
               const float* __restrict__ trans,
               float*       __restrict__ out)
{
    __shared__ __align__(16) float2 sp[2][2][32];   // [warp][buffer][pair]
    __shared__ float2 fin[2][32];
    __shared__ int    ktW[2];

    const int w    = threadIdx.x >> 5;              // 0 = fwd, 1 = bwd
    const int lane = threadIdx.x & 31;

    // ---- snake rank -> bid mapping over bid%148 SM residue classes ----
    const int c = blockIdx.x;                       // grid = 512
    const int q = c / 148;
    const int s = c - q * 148;
    int rank;
    if      (q == 0) rank = s;                      //   0..147 (longest)
    else if (q == 1) rank = 295 - s;                // 148..295
    else if (q == 2) rank = 296 + s;                // 296..443
    else             rank = 511 - s;                // 444..511 (s < 68)
    const int b = d_perm[rank];

    const uint32_t b0a = smem_u32(sp[w][0]);
    const uint32_t b1a = smem_u32(sp[w][1]);
    u64* wr0 = reinterpret_cast<u64*>(sp[w][0]);
    u64* wr1 = reinterpret_cast<u64*>(sp[w][1]);

    const int len = lens[b];
    const int m   = len >> 1;                       // fwd steps; bwd = len-m

    // ---- E in registers: fwd = rows of exp(trans); bwd = columns ----
    u64 Ea[32], Eb[32];
    if (w == 0) {
        const float* ra = trans + (2 * lane)     * CRF_L;
        const float* rb = trans + (2 * lane + 1) * CRF_L;
#pragma unroll
        for (int jj = 0; jj < 32; jj++) {
            Ea[jj] = packf2(expf(ra[2 * jj]), expf(ra[2 * jj + 1]));
            Eb[jj] = packf2(expf(rb[2 * jj]), expf(rb[2 * jj + 1]));
        }
    } else {
        const float* ca = trans + (2 * lane);       // column 2*lane
        const float* cb = trans + (2 * lane + 1);   // column 2*lane+1
#pragma unroll
        for (int jj = 0; jj < 32; jj++) {
            Ea[jj] = packf2(expf(ca[(2 * jj) * CRF_L]), expf(ca[(2 * jj + 1) * CRF_L]));
            Eb[jj] = packf2(expf(cb[(2 * jj) * CRF_L]), expf(cb[(2 * jj + 1) * CRF_L]));
        }
    }

    const float2* base =
        reinterpret_cast<const float2*>(logits + (size_t)b * CRF_T * CRF_L) + lane;

    int kt;
    int nsteps;

    if (w == 0) {
        // ---- forward: init = delta at start label 62, m logit steps ----
        wr0[lane] = packf2((2 * lane == 62) ? 1.0f : 0.0f,
                           (2 * lane + 1 == 62) ? 1.0f : 0.0f);
        __syncwarp();
        kt = run_chain<+1>(base, m, false, Ea, Eb, b0a, b1a, lane);
        nsteps = m;
    } else {
        // ---- backward: init v = el_{len-1} .* e63 (or e63 if len==0) ----
        float e63x = expf(trans[63 * CRF_L + 2 * lane]);
        float e63y = expf(trans[63 * CRF_L + 2 * lane + 1]);
        if (len >= 1) {
            float2 lgl = __ldg(base + (ptrdiff_t)(len - 1) * 32);
            e63x *= expf(lgl.x);
            e63y *= expf(lgl.y);
        }
        wr0[lane] = packf2(e63x, e63y);
        __syncwarp();
        const int nlog = (len >= 1) ? (len - m - 1) : 0;
        const float2* lgb = base + (ptrdiff_t)(len - 2) * 32;
        kt = run_chain<-1>(lgb, nlog, len >= 1, Ea, Eb, b0a, b1a, lane);
        nsteps = (len >= 1) ? (nlog + 1) : 0;
    }

    // ---- combine: logZ = (ktF+ktB)*ln2 + log( sum_j pF[j] * pB[j] ) ----
    float px, py;
    unpackf2((nsteps & 1) ? wr1[lane] : wr0[lane], px, py);
    fin[w][lane] = make_float2(px, py);
    if (lane == 0) ktW[w] = kt;
    __syncthreads();

    if (w == 0) {
        float2 f = fin[0][lane];
        float2 g = fin[1][lane];
        float dot = f.x * g.x + f.y * g.y;
#pragma unroll
        for (int o = 16; o > 0; o >>= 1)
            dot += __shfl_xor_sync(FULLM, dot, o);
        if (lane == 0)
            out[b] = (float)(ktW[0] + ktW[1]) * C_LN2 + __logf(dot);
    }
}

extern "C" void kernel_launch(void* const* d_in, const int* in_sizes, int n_in,
                              void* d_out, int out_size)
{
    const float* logits = (const float*)d_in[0];   // [512,1024,64] f32
    const int*   lens   = (const int*)  d_in[1];   // [512] i32
    const float* trans  = (const float*)d_in[2];   // [64,64] f32
    float* out = (float*)d_out;                    // [512] f32

    rank_kernel<<<1, CRF_B>>>(lens);
    crf_fwd_kernel<<<CRF_B, 64>>>(logits, lens, trans, out);
}

// round 14
// speedup vs baseline: 1.2366x; 1.0966x over previous
#include <cuda_runtime.h>
#include <cstdint>
#include <cstddef>

// CRF forward log-partition. B=512, T=1024, L=64.
// Fwd/bwd split (halves the serial chain) + length-aware placement +
// full-SMSP spread:
//  - pre-kernel ranks batches by len desc (exact O(n^2) count -> d_perm).
//  - 256 CTAs x 128 threads; CTA owns ranks {2p, 2p+1} (similar lengths):
//      warp0: fwd A | warp1: bwd A | warp2: fwd B | warp3: bwd B
//    -> one working warp per SMSP; 254 regs -> 2 CTAs/SM, all resident.
//  - placement over bid%148 residue classes: bids 108..147 are the SMs that
//    host ONE CTA -> give them the 40 longest pairs (critical chain runs on
//    a private SMSP). Two-CTA SMs get pairs (p+40, 255-p): work ~433 const.
// Step core = R11 verbatim: source-forced 16x ld.shared.v2.b64 front-batch,
// 8 named f32x2 accumulators, deferred 4-step exact power-of-2 rescale.
// logZ = (ktF+ktB)*ln2 + log( sum_j pF[j] * pB[j] ).

#define CRF_B 512
#define CRF_T 1024
#define CRF_L 64
#define C_LOG2E 1.4426950408889634f
#define C_LN2   0.6931471805599453f
#define FULLM  0xffffffffu

using u64 = unsigned long long;

__device__ int d_perm[CRF_B];            // rank -> batch index

__device__ __forceinline__ float ex2f(float x) {
    float r; asm("ex2.approx.f32 %0, %1;" : "=f"(r) : "f"(x)); return r;
}
__device__ __forceinline__ u64 packf2(float lo, float hi) {
    u64 r; asm("mov.b64 %0, {%1, %2};" : "=l"(r) : "f"(lo), "f"(hi)); return r;
}
__device__ __forceinline__ void unpackf2(u64 v, float& lo, float& hi) {
    asm("mov.b64 {%0, %1}, %2;" : "=f"(lo), "=f"(hi) : "l"(v));
}
__device__ __forceinline__ uint32_t smem_u32(const void* p) {
    uint32_t a;
    asm("{ .reg .u64 t; cvta.to.shared.u64 t, %1; cvt.u32.u64 %0, t; }"
        : "=r"(a) : "l"(p));
    return a;
}
#define FMA2(acc, a, b) \
    asm("fma.rn.f32x2 %0, %1, %2, %0;" : "+l"(acc) : "l"(a), "l"(b))
#define ADD2(acc, a) \
    asm("add.rn.f32x2 %0, %0, %1;" : "+l"(acc) : "l"(a))
#define LDSV2(lo, hi, addr) \
    asm volatile("ld.shared.v2.b64 {%0, %1}, [%2];" \
                 : "=l"(lo), "=l"(hi) : "r"(addr))

// ---- pre-kernel: exact descending-length ranking (O(n^2) count) ----
__global__ void __launch_bounds__(CRF_B)
rank_kernel(const int* __restrict__ lens)
{
    __shared__ int sl[CRF_B];
    const int i = threadIdx.x;
    sl[i] = lens[i];
    __syncthreads();
    const int li = sl[i];
    int cnt = 0;
#pragma unroll 8
    for (int j = 0; j < CRF_B; j++) {
        int lj = sl[j];
        cnt += (lj > li) || (lj == li && j < i);
    }
    d_perm[cnt] = i;                      // bijection: rank -> batch
}

// ---- R11 step, verbatim ----
template <bool FOLD, bool REC>
__device__ __forceinline__ void crf_step(
    float2 lg,
    const u64 (&Ea)[32], const u64 (&Eb)[32],
    uint32_t rda, uint32_t wra,
    int lane, int& ktot, unsigned& mu)
{
    float elA = ex2f(lg.x * C_LOG2E);
    float elB = ex2f(lg.y * C_LOG2E);
    if (FOLD) {
        int k = (int)(mu >> 23) - 127;
        ktot += k;
        float s = __int_as_float((127 - k) << 23);   // exact 2^-k
        elA *= s;
        elB *= s;
    }

    u64 p[32];
#pragma unroll
    for (int i = 0; i < 16; i++)
        LDSV2(p[2 * i], p[2 * i + 1], rda + 16u * i);

    u64 a0 = 0ull, a1 = 0ull, a2 = 0ull, a3 = 0ull;
    u64 b0 = 0ull, b1 = 0ull, b2 = 0ull, b3 = 0ull;
#pragma unroll
    for (int jj = 0; jj < 32; jj += 4) {
        FMA2(a0, Ea[jj],     p[jj]);
        FMA2(b0, Eb[jj],     p[jj]);
        FMA2(a1, Ea[jj + 1], p[jj + 1]);
        FMA2(b1, Eb[jj + 1], p[jj + 1]);
        FMA2(a2, Ea[jj + 2], p[jj + 2]);
        FMA2(b2, Eb[jj + 2], p[jj + 2]);
        FMA2(a3, Ea[jj + 3], p[jj + 3]);
        FMA2(b3, Eb[jj + 3], p[jj + 3]);
    }
    ADD2(a0, a1); ADD2(a2, a3); ADD2(a0, a2);
    ADD2(b0, b1); ADD2(b2, b3); ADD2(b0, b2);
    float ax, ay, bx, by;
    unpackf2(a0, ax, ay);
    unpackf2(b0, bx, by);
    float pA = (ax + ay) * elA;
    float pB = (bx + by) * elB;

    asm volatile("st.shared.b64 [%0], %1;"
                 :: "r"(wra + 8u * (uint32_t)lane), "l"(packf2(pA, pB)));

    if (REC) {
        mu = __reduce_max_sync(FULLM, __float_as_uint(fmaxf(pA, pB)));
    }
    __syncwarp();
}

template <int SGN>
__device__ __forceinline__ int run_chain(
    const float2* __restrict__ lgp, int nlog, bool bare,
    const u64 (&Ea)[32], const u64 (&Eb)[32],
    uint32_t b0a, uint32_t b1a, int lane)
{
    int      ktot = 0;
    unsigned mu   = 0x3f800000u;           // 1.0f bits -> first fold k=0

    float2 q0, q1, q2, q3;
    if (nlog > 0) q0 = __ldg(lgp);
    if (nlog > 1) q1 = __ldg(lgp + SGN * 32);
    if (nlog > 2) q2 = __ldg(lgp + SGN * 64);
    if (nlog > 3) q3 = __ldg(lgp + SGN * 96);

    int t = 0;
    for (; t + 4 <= nlog; t += 4) {
        float2 g;
        g = q0; if (t + 4 < nlog) q0 = __ldg(lgp + (ptrdiff_t)SGN * (t + 4) * 32);
        crf_step<true,  false>(g, Ea, Eb, b0a, b1a, lane, ktot, mu);
        g = q1; if (t + 5 < nlog) q1 = __ldg(lgp + (ptrdiff_t)SGN * (t + 5) * 32);
        crf_step<false, false>(g, Ea, Eb, b1a, b0a, lane, ktot, mu);
        g = q2; if (t + 6 < nlog) q2 = __ldg(lgp + (ptrdiff_t)SGN * (t + 6) * 32);
        crf_step<false, false>(g, Ea, Eb, b0a, b1a, lane, ktot, mu);
        g = q3; if (t + 7 < nlog) q3 = __ldg(lgp + (ptrdiff_t)SGN * (t + 7) * 32);
        crf_step<false, true >(g, Ea, Eb, b1a, b0a, lane, ktot, mu);
    }

    bool pend = (t > 0);
    if (t < nlog) {
        if (pend) crf_step<true,  false>(q0, Ea, Eb, b0a, b1a, lane, ktot, mu);
        else      crf_step<false, false>(q0, Ea, Eb, b0a, b1a, lane, ktot, mu);
        pend = false; t++;
    }
    if (t < nlog) { crf_step<false, false>(q1, Ea, Eb, b1a, b0a, lane, ktot, mu); t++; }
    if (t < nlog) { crf_step<false, false>(q2, Ea, Eb, b0a, b1a, lane, ktot, mu); t++; }

    if (bare) {
        float2 g = make_float2(0.0f, 0.0f);
        bool odd = (t & 1);
        if (pend) {
            if (odd) crf_step<true, false>(g, Ea, Eb, b1a, b0a, lane, ktot, mu);
            else     crf_step<true, false>(g, Ea, Eb, b0a, b1a, lane, ktot, mu);
        } else {
            if (odd) crf_step<false, false>(g, Ea, Eb, b1a, b0a, lane, ktot, mu);
            else     crf_step<false, false>(g, Ea, Eb, b0a, b1a, lane, ktot, mu);
        }
    }
    return ktot;
}

__global__ void __launch_bounds__(128)
crf_fwd_kernel(const float* __restrict__ logits,
               const int*   __restrict__ lens,
               const float* __restrict__ trans,
               float*       __restrict__ out)
{
    __shared__ __align__(16) float2 sp[4][2][32];   // [warp][buffer][pair]
    __shared__ float2 fin[4][32];
    __shared__ int    ktW[4];

    const int w    = threadIdx.x >> 5;              // 0..3
    const int lane = threadIdx.x & 31;
    const int dir  = w & 1;                         // 0 = fwd, 1 = bwd

    // ---- placement: bid -> pair of ranks {2*pair, 2*pair+1} ----
    // SMs hosting bids 108..147 get exactly one CTA (256 CTAs on 148
    // residue classes) -> give them the 40 longest pairs. Two-CTA SMs get
    // (p+40, 255-p): per-SM work ~433 steps, balanced.
    const int bid = blockIdx.x;                     // grid = 256
    int pair;
    if (bid >= 108 && bid < 148) pair = bid - 108;  // pairs 0..39 (longest)
    else if (bid < 108)          pair = bid + 40;   // pairs 40..147
    else                         pair = 255 - (bid - 148); // pairs 255..148
    const int b = d_perm[2 * pair + (w >> 1)];

    const uint32_t b0a = smem_u32(sp[w][0]);
    const uint32_t b1a = smem_u32(sp[w][1]);
    u64* wr0 = reinterpret_cast<u64*>(sp[w][0]);
    u64* wr1 = reinterpret_cast<u64*>(sp[w][1]);

    const int len = lens[b];
    const int m   = len >> 1;                       // fwd steps; bwd = len-m

    // ---- E in registers: fwd = rows of exp(trans); bwd = columns ----
    u64 Ea[32], Eb[32];
    if (dir == 0) {
        const float* ra = trans + (2 * lane)     * CRF_L;
        const float* rb = trans + (2 * lane + 1) * CRF_L;
#pragma unroll
        for (int jj = 0; jj < 32; jj++) {
            Ea[jj] = packf2(expf(ra[2 * jj]), expf(ra[2 * jj + 1]));
            Eb[jj] = packf2(expf(rb[2 * jj]), expf(rb[2 * jj + 1]));
        }
    } else {
        const float* ca = trans + (2 * lane);       // column 2*lane
        const float* cb = trans + (2 * lane + 1);   // column 2*lane+1
#pragma unroll
        for (int jj = 0; jj < 32; jj++) {
            Ea[jj] = packf2(expf(ca[(2 * jj) * CRF_L]), expf(ca[(2 * jj + 1) * CRF_L]));
            Eb[jj] = packf2(expf(cb[(2 * jj) * CRF_L]), expf(cb[(2 * jj + 1) * CRF_L]));
        }
    }

    const float2* base =
        reinterpret_cast<const float2*>(logits + (size_t)b * CRF_T * CRF_L) + lane;

    int kt;
    int nsteps;

    if (dir == 0) {
        // ---- forward: init = delta at start label 62, m logit steps ----
        wr0[lane] = packf2((2 * lane == 62) ? 1.0f : 0.0f,
                           (2 * lane + 1 == 62) ? 1.0f : 0.0f);
        __syncwarp();
        kt = run_chain<+1>(base, m, false, Ea, Eb, b0a, b1a, lane);
        nsteps = m;
    } else {
        // ---- backward: init v = el_{len-1} .* e63 (or e63 if len==0) ----
        float e63x = expf(trans[63 * CRF_L + 2 * lane]);
        float e63y = expf(trans[63 * CRF_L + 2 * lane + 1]);
        if (len >= 1) {
            float2 lgl = __ldg(base + (ptrdiff_t)(len - 1) * 32);
            e63x *= expf(lgl.x);
            e63y *= expf(lgl.y);
        }
        wr0[lane] = packf2(e63x, e63y);
        __syncwarp();
        const int nlog = (len >= 1) ? (len - m - 1) : 0;
        const float2* lgb = base + (ptrdiff_t)(len - 2) * 32;
        kt = run_chain<-1>(lgb, nlog, len >= 1, Ea, Eb, b0a, b1a, lane);
        nsteps = (len >= 1) ? (nlog + 1) : 0;
    }

    // ---- combine per batch: logZ = (ktF+ktB)*ln2 + log(sum pF[j]*pB[j]) ----
    float px, py;
    unpackf2((nsteps & 1) ? wr1[lane] : wr0[lane], px, py);
    fin[w][lane] = make_float2(px, py);
    if (lane == 0) ktW[w] = kt;
    __syncthreads();

    if (dir == 0) {
        float2 f = fin[w][lane];
        float2 g = fin[w + 1][lane];
        float dot = f.x * g.x + f.y * g.y;
#pragma unroll
        for (int o = 16; o > 0; o >>= 1)
            dot += __shfl_xor_sync(FULLM, dot, o);
        if (lane == 0)
            out[b] = (float)(ktW[w] + ktW[w + 1]) * C_LN2 + __logf(dot);
    }
}

extern "C" void kernel_launch(void* const* d_in, const int* in_sizes, int n_in,
                              void* d_out, int out_size)
{
    const float* logits = (const float*)d_in[0];   // [512,1024,64] f32
    const int*   lens   = (const int*)  d_in[1];   // [512] i32
    const float* trans  = (const float*)d_in[2];   // [64,64] f32
    float* out = (float*)d_out;                    // [512] f32

    rank_kernel<<<1, CRF_B>>>(lens);
    crf_fwd_kernel<<<CRF_B / 2, 128>>>(logits, lens, trans, out);
}